// round 1
// baseline (speedup 1.0000x reference)
#include <cuda_runtime.h>
#include <math.h>

#define Bn 256
#define Tn 128
#define Fn 1024
#define Hn 512
#define IN1 1152   // T + 2H
#define FT 128     // f tile per block in k2
#define KC 32      // k chunk
#define PW 132     // sW pitch (floats), 16B-aligned rows
#define PX 132     // sX pitch

__device__ float g_c[Bn * Tn];   // c[b,t]
__device__ float g_e[Bn * Fn];   // logits e[b,f]

typedef unsigned long long ull;

__device__ __forceinline__ ull dup2(float a) {
    ull r;
    asm("mov.b64 %0, {%1, %1};" : "=l"(r) : "f"(a));
    return r;
}
__device__ __forceinline__ void fma2(ull &d, ull a, ull b) {
    asm("fma.rn.f32x2 %0, %1, %2, %3;" : "=l"(d) : "l"(a), "l"(b), "l"(d));
}

union F4U { float4 v; ull u[2]; };
union UF  { ull u; float f[2]; };

// ---------------------------------------------------------------------------
// k1: c[b,t] = b1[t] + sum_{j<1024} W1[t][128+j] * concat(h,s)[b][j]
// grid = B blocks, T threads. hs staged in smem; W1 (590KB) stays L2-resident.
// ---------------------------------------------------------------------------
__global__ void k1_c(const float* __restrict__ h, const float* __restrict__ s,
                     const float* __restrict__ W1, const float* __restrict__ b1) {
    __shared__ float hs[2 * Hn];
    int b = blockIdx.x, t = threadIdx.x;
    const float4* h4 = (const float4*)(h + (size_t)b * Hn);
    const float4* s4 = (const float4*)(s + (size_t)b * Hn);
    for (int i = t; i < Hn / 4; i += Tn) {
        ((float4*)hs)[i]           = __ldg(&h4[i]);
        ((float4*)hs)[Hn / 4 + i]  = __ldg(&s4[i]);
    }
    __syncthreads();
    const float4* w4 = (const float4*)(W1 + (size_t)t * IN1 + Tn);
    float acc = 0.f;
    #pragma unroll 8
    for (int j = 0; j < (2 * Hn) / 4; j++) {
        float4 w = __ldg(&w4[j]);
        float4 v = ((const float4*)hs)[j];
        acc += w.x * v.x + w.y * v.y + w.z * v.z + w.w * v.w;
    }
    g_c[b * Tn + t] = acc + b1[t];
}

// ---------------------------------------------------------------------------
// k2: per (b, f0): U[t,f] = sum_{t'} W1[t,t'] * x[b,t',f]; then
//     e[b,f] = b2 + sum_t W2[t] * tanh(U[t,f] + c[b,t])
// 256 threads as 16x16; thread tile 8t x 8f; f32x2 packed FMAs.
// ---------------------------------------------------------------------------
__global__ __launch_bounds__(256, 2) void k2_main(
    const float* __restrict__ x, const float* __restrict__ W1,
    const float* __restrict__ W2, const float* __restrict__ b2) {
    __shared__ float sW[KC][PW];    // sW[k][t] = W1[t][kc+k] (transposed)
    __shared__ float sX[KC][PX];    // sX[k][fl] = x[b][kc+k][f0+fl]
    __shared__ float c_s[Tn];
    __shared__ float w2_s[Tn];
    __shared__ float red[16][FT];

    int tid = threadIdx.x;
    int tx = tid & 15, ty = tid >> 4;
    int b  = blockIdx.y;
    int f0 = blockIdx.x * FT;

    if (tid < Tn) {
        c_s[tid]  = g_c[b * Tn + tid];
        w2_s[tid] = W2[tid];
    }

    ull acc[8][4];
    #pragma unroll
    for (int i = 0; i < 8; i++)
        #pragma unroll
        for (int j = 0; j < 4; j++) acc[i][j] = 0ull;

    const float* xb = x + (size_t)b * Tn * Fn + f0;

    for (int kc = 0; kc < Tn; kc += KC) {
        __syncthreads();   // protect smem from previous chunk's readers
        // load W1 chunk transposed: coalesced reads along k within each row t
        #pragma unroll
        for (int l = 0; l < (KC * Tn) / 256; l++) {
            int idx = l * 256 + tid;
            int kk  = idx & (KC - 1);
            int t   = idx >> 5;
            sW[kk][t] = W1[(size_t)t * IN1 + kc + kk];
        }
        // load x chunk: float4 coalesced, conflict-free stores
        #pragma unroll
        for (int l = 0; l < (KC * FT) / (256 * 4); l++) {
            int idx4 = l * 256 + tid;
            int fl4  = idx4 & 31;
            int k    = idx4 >> 5;
            float4 v = __ldg((const float4*)(xb + (size_t)(kc + k) * Fn) + fl4);
            *(float4*)&sX[k][fl4 * 4] = v;
        }
        __syncthreads();

        #pragma unroll 8
        for (int k = 0; k < KC; k++) {
            F4U a0, a1, bb0, bb1;
            a0.v  = *(const float4*)&sW[k][ty * 8];
            a1.v  = *(const float4*)&sW[k][ty * 8 + 4];
            bb0.v = *(const float4*)&sX[k][tx * 8];
            bb1.v = *(const float4*)&sX[k][tx * 8 + 4];
            ull bq[4] = { bb0.u[0], bb0.u[1], bb1.u[0], bb1.u[1] };
            float av[8] = { a0.v.x, a0.v.y, a0.v.z, a0.v.w,
                            a1.v.x, a1.v.y, a1.v.z, a1.v.w };
            #pragma unroll
            for (int i = 0; i < 8; i++) {
                ull ad = dup2(av[i]);
                #pragma unroll
                for (int j = 0; j < 4; j++) fma2(acc[i][j], ad, bq[j]);
            }
        }
    }
    __syncthreads();

    // fused epilogue: +c, tanh, *W2, partial sum over this thread's 8 t values
    float ef[8];
    #pragma unroll
    for (int j = 0; j < 8; j++) ef[j] = 0.f;
    #pragma unroll
    for (int i = 0; i < 8; i++) {
        int t = ty * 8 + i;
        float cv = c_s[t];
        float wv = w2_s[t];
        #pragma unroll
        for (int j = 0; j < 4; j++) {
            UF u; u.u = acc[i][j];
            ef[2 * j]     += wv * tanhf(u.f[0] + cv);
            ef[2 * j + 1] += wv * tanhf(u.f[1] + cv);
        }
    }
    #pragma unroll
    for (int j = 0; j < 8; j++) red[ty][tx * 8 + j] = ef[j];
    __syncthreads();
    if (tid < FT) {
        float e = b2[0];
        #pragma unroll
        for (int r = 0; r < 16; r++) e += red[r][tid];
        g_e[b * Fn + f0 + tid] = e;
    }
}

// ---------------------------------------------------------------------------
// k3: out[b,f] = softmax over f of e[b,f]
// ---------------------------------------------------------------------------
__global__ void k3_softmax(float* __restrict__ out) {
    __shared__ float sm[256];
    int b = blockIdx.x, tid = threadIdx.x;
    const float* eb = g_e + b * Fn;
    float v[4];
    float m = -1e30f;
    #pragma unroll
    for (int i = 0; i < 4; i++) { v[i] = eb[tid + i * 256]; m = fmaxf(m, v[i]); }
    sm[tid] = m; __syncthreads();
    for (int st = 128; st > 0; st >>= 1) {
        if (tid < st) sm[tid] = fmaxf(sm[tid], sm[tid + st]);
        __syncthreads();
    }
    m = sm[0];
    __syncthreads();
    float sum = 0.f;
    #pragma unroll
    for (int i = 0; i < 4; i++) { v[i] = __expf(v[i] - m); sum += v[i]; }
    sm[tid] = sum; __syncthreads();
    for (int st = 128; st > 0; st >>= 1) {
        if (tid < st) sm[tid] += sm[tid + st];
        __syncthreads();
    }
    float inv = 1.f / sm[0];
    #pragma unroll
    for (int i = 0; i < 4; i++) out[b * Fn + tid + i * 256] = v[i] * inv;
}

extern "C" void kernel_launch(void* const* d_in, const int* in_sizes, int n_in,
                              void* d_out, int out_size) {
    const float* h  = (const float*)d_in[0];
    const float* s  = (const float*)d_in[1];
    const float* x  = (const float*)d_in[2];
    const float* W1 = (const float*)d_in[3];
    const float* b1 = (const float*)d_in[4];
    const float* W2 = (const float*)d_in[5];
    const float* b2 = (const float*)d_in[6];
    float* out = (float*)d_out;

    k1_c<<<Bn, Tn>>>(h, s, W1, b1);
    dim3 g2(Fn / FT, Bn);
    k2_main<<<g2, 256>>>(x, W1, W2, b2);
    k3_softmax<<<Bn, 256>>>(out);
}

// round 2
// speedup vs baseline: 1.0804x; 1.0804x over previous
#include <cuda_runtime.h>
#include <math.h>

#define Bn 256
#define Tn 128
#define Fn 1024
#define Hn 512
#define IN1 1152   // T + 2H
#define FT 128     // f tile per block in k2
#define KC 32      // k chunk
#define PWD 260    // sWd pitch in floats (duplicated row: 256 + pad, %4==0)
#define PX 132     // sX pitch in floats (%4==0, conflict-free)

__device__ float g_c[Bn * Tn];   // c[b,t]
__device__ float g_e[Bn * Fn];   // logits e[b,f]

typedef unsigned long long ull;

__device__ __forceinline__ void fma2(ull &d, ull a, ull b) {
    asm("fma.rn.f32x2 %0, %1, %2, %3;" : "=l"(d) : "l"(a), "l"(b), "l"(d));
}
__device__ __forceinline__ float tanh_fast(float x) {
    float y;
    asm("tanh.approx.f32 %0, %1;" : "=f"(y) : "f"(x));
    return y;
}

union F4U { float4 v; ull u[2]; };
union UF  { ull u; float f[2]; };

// ---------------------------------------------------------------------------
// k1: c[b,t] = b1[t] + sum_{j<1024} W1[t][128+j] * concat(h,s)[b][j]
// Block handles 4 batches (hs in smem, broadcast); W1 row segment loaded once
// per thread and reused across the 4 batches. grid=64, block=256.
// Thread = (t = tid>>1, half = tid&1); halves interleave float4s so adjacent
// lanes share 32B sectors. Pair-reduce via shfl.
// ---------------------------------------------------------------------------
#define BT1 4
__global__ __launch_bounds__(256) void k1_c(
    const float* __restrict__ h, const float* __restrict__ s,
    const float* __restrict__ W1, const float* __restrict__ b1) {
    __shared__ float hs[BT1 * 1024];
    int tid = threadIdx.x;
    int b0 = blockIdx.x * BT1;

    // stage hs: 1024 float4 total
    for (int i = tid; i < BT1 * 256; i += 256) {
        int bb = i >> 8, j4 = i & 255;
        float4 v;
        if (j4 < 128) v = __ldg((const float4*)(h + (size_t)(b0 + bb) * Hn) + j4);
        else          v = __ldg((const float4*)(s + (size_t)(b0 + bb) * Hn) + (j4 - 128));
        ((float4*)hs)[bb * 256 + j4] = v;
    }
    __syncthreads();

    int t = tid >> 1, half = tid & 1;
    const float4* w4 = (const float4*)(W1 + (size_t)t * IN1 + Tn);
    float acc[BT1] = {0.f, 0.f, 0.f, 0.f};

    #pragma unroll 4
    for (int j = 0; j < 128; j++) {
        int idx4 = 2 * j + half;           // interleaved: lanes share sectors
        float4 w = __ldg(&w4[idx4]);
        #pragma unroll
        for (int bb = 0; bb < BT1; bb++) {
            float4 v = ((const float4*)hs)[bb * 256 + idx4];
            acc[bb] += w.x * v.x + w.y * v.y + w.z * v.z + w.w * v.w;
        }
    }
    #pragma unroll
    for (int bb = 0; bb < BT1; bb++)
        acc[bb] += __shfl_xor_sync(0xffffffffu, acc[bb], 1);
    if (!half) {
        float bias = b1[t];
        #pragma unroll
        for (int bb = 0; bb < BT1; bb++)
            g_c[(b0 + bb) * Tn + t] = acc[bb] + bias;
    }
}

// ---------------------------------------------------------------------------
// k2: per (b, f0): U[t,f] = sum_{t'} W1[t,t'] * x[b,t',f]; then
//     e[b,f] = b2 + sum_t W2[t] * tanh(U[t,f] + c[b,t])
// 256 threads as 16x16; thread tile 8t x 8f (split 4+4 at stride 64).
// W1 stored DUPLICATED in smem so LDS.128 yields f32x2-ready (w,w) pairs.
// Dynamic smem: sWd [32][260] | sX [32][132] (aliased as red [16][132]) | c,w2
// ---------------------------------------------------------------------------
#define SM_WD 0
#define SM_X  (KC * PWD)
#define SM_CW (KC * PWD + KC * PX)
#define SM_TOT_FLOATS (KC * PWD + KC * PX + 2 * Tn)

__global__ __launch_bounds__(256, 2) void k2_main(
    const float* __restrict__ x, const float* __restrict__ W1,
    const float* __restrict__ W2, const float* __restrict__ b2) {
    extern __shared__ float sm[];
    float* sWd  = sm + SM_WD;     // [KC][PWD], duplicated along t
    float* sX   = sm + SM_X;      // [KC][PX]
    float* red  = sm + SM_X;      // alias, [16][PX], used after mainloop
    float* c_s  = sm + SM_CW;     // [Tn]
    float* w2_s = sm + SM_CW + Tn;

    int tid = threadIdx.x;
    int tx = tid & 15, ty = tid >> 4;
    int b  = blockIdx.y;
    int f0 = blockIdx.x * FT;

    if (tid < Tn) {
        c_s[tid]  = g_c[b * Tn + tid];
        w2_s[tid] = W2[tid];
    }

    ull acc[8][4];
    #pragma unroll
    for (int i = 0; i < 8; i++)
        #pragma unroll
        for (int j = 0; j < 4; j++) acc[i][j] = 0ull;

    const float* xb = x + (size_t)b * Tn * Fn + f0;

    for (int kc = 0; kc < Tn; kc += KC) {
        __syncthreads();   // protect smem from previous chunk's readers
        // stage W1 chunk duplicated: sWd[kk][2t]=sWd[kk][2t+1]=W1[t][kc+kk]
        // kk fast within warp -> coalesced global; float2 stores ~conflict-free
        #pragma unroll
        for (int l = 0; l < (KC * Tn) / 256; l++) {
            int idx = l * 256 + tid;
            int kk  = idx & (KC - 1);
            int t   = idx >> 5;
            float w = __ldg(&W1[(size_t)t * IN1 + kc + kk]);
            float2 d2; d2.x = w; d2.y = w;
            *(float2*)&sWd[kk * PWD + 2 * t] = d2;
        }
        // stage x chunk: float4 coalesced, conflict-free stores
        #pragma unroll
        for (int l = 0; l < (KC * FT) / (256 * 4); l++) {
            int idx4 = l * 256 + tid;
            int fl4  = idx4 & 31;
            int k    = idx4 >> 5;
            float4 v = __ldg((const float4*)(xb + (size_t)(kc + k) * Fn) + fl4);
            *(float4*)&sX[k * PX + fl4 * 4] = v;
        }
        __syncthreads();

        #pragma unroll 8
        for (int k = 0; k < KC; k++) {
            // a: 4x LDS.128 of duplicated W -> 8 (w,w) pairs, no MOVs
            F4U a0, a1, a2, a3, bb0, bb1;
            const float* wr = &sWd[k * PWD];
            a0.v = *(const float4*)&wr[8 * ty];            // t = 4ty, 4ty+1
            a1.v = *(const float4*)&wr[8 * ty + 4];        // t = 4ty+2, 4ty+3
            a2.v = *(const float4*)&wr[128 + 8 * ty];      // t = 64+4ty, +1
            a3.v = *(const float4*)&wr[128 + 8 * ty + 4];  // t = 64+4ty+2, +3
            const float* xr = &sX[k * PX];
            bb0.v = *(const float4*)&xr[4 * tx];           // f = 4tx..4tx+3
            bb1.v = *(const float4*)&xr[64 + 4 * tx];      // f = 64+4tx..+3
            ull ad[8] = { a0.u[0], a0.u[1], a1.u[0], a1.u[1],
                          a2.u[0], a2.u[1], a3.u[0], a3.u[1] };
            ull bq[4] = { bb0.u[0], bb0.u[1], bb1.u[0], bb1.u[1] };
            #pragma unroll
            for (int i = 0; i < 8; i++)
                #pragma unroll
                for (int j = 0; j < 4; j++) fma2(acc[i][j], ad[i], bq[j]);
        }
    }
    __syncthreads();

    // fused epilogue: +c, tanh, *W2, partial sum over this thread's 8 t values
    float ef[8];
    #pragma unroll
    for (int m = 0; m < 8; m++) ef[m] = 0.f;
    #pragma unroll
    for (int i = 0; i < 8; i++) {
        int t = (i < 4) ? (4 * ty + i) : (64 + 4 * ty + (i - 4));
        float cv = c_s[t];
        float wv = w2_s[t];
        #pragma unroll
        for (int j = 0; j < 4; j++) {
            UF u; u.u = acc[i][j];
            ef[2 * j]     += wv * tanh_fast(u.f[0] + cv);
            ef[2 * j + 1] += wv * tanh_fast(u.f[1] + cv);
        }
    }
    #pragma unroll
    for (int m = 0; m < 8; m++) {
        int fl = (m < 4) ? (4 * tx + m) : (64 + 4 * tx + (m - 4));
        red[ty * PX + fl] = ef[m];
    }
    __syncthreads();
    if (tid < FT) {
        float e = b2[0];
        #pragma unroll
        for (int r = 0; r < 16; r++) e += red[r * PX + tid];
        g_e[b * Fn + f0 + tid] = e;
    }
}

// ---------------------------------------------------------------------------
// k3: out[b,f] = softmax over f of e[b,f]
// ---------------------------------------------------------------------------
__global__ void k3_softmax(float* __restrict__ out) {
    __shared__ float smr[256];
    int b = blockIdx.x, tid = threadIdx.x;
    const float* eb = g_e + b * Fn;
    float v[4];
    float m = -1e30f;
    #pragma unroll
    for (int i = 0; i < 4; i++) { v[i] = eb[tid + i * 256]; m = fmaxf(m, v[i]); }
    smr[tid] = m; __syncthreads();
    for (int st = 128; st > 0; st >>= 1) {
        if (tid < st) smr[tid] = fmaxf(smr[tid], smr[tid + st]);
        __syncthreads();
    }
    m = smr[0];
    __syncthreads();
    float sum = 0.f;
    #pragma unroll
    for (int i = 0; i < 4; i++) { v[i] = __expf(v[i] - m); sum += v[i]; }
    smr[tid] = sum; __syncthreads();
    for (int st = 128; st > 0; st >>= 1) {
        if (tid < st) smr[tid] += smr[tid + st];
        __syncthreads();
    }
    float inv = 1.f / smr[0];
    #pragma unroll
    for (int i = 0; i < 4; i++) out[b * Fn + tid + i * 256] = v[i] * inv;
}

extern "C" void kernel_launch(void* const* d_in, const int* in_sizes, int n_in,
                              void* d_out, int out_size) {
    const float* h  = (const float*)d_in[0];
    const float* s  = (const float*)d_in[1];
    const float* x  = (const float*)d_in[2];
    const float* W1 = (const float*)d_in[3];
    const float* b1 = (const float*)d_in[4];
    const float* W2 = (const float*)d_in[5];
    const float* b2 = (const float*)d_in[6];
    float* out = (float*)d_out;

    static int smem_set = 0;
    if (!smem_set) {
        cudaFuncSetAttribute(k2_main, cudaFuncAttributeMaxDynamicSharedMemorySize,
                             SM_TOT_FLOATS * (int)sizeof(float));
        smem_set = 1;
    }

    k1_c<<<Bn / BT1, 256>>>(h, s, W1, b1);
    dim3 g2(Fn / FT, Bn);
    k2_main<<<g2, 256, SM_TOT_FLOATS * sizeof(float)>>>(x, W1, W2, b2);
    k3_softmax<<<Bn, 256>>>(out);
}

// round 4
// speedup vs baseline: 2.2024x; 2.0386x over previous
#include <cuda_runtime.h>
#include <math.h>
#include <stdint.h>

#define Bn 256
#define Tn 128
#define Fn 1024
#define Hn 512
#define IN1 1152
#define KSP 4          // k1 K-splits

__device__ float g_cp[KSP][Bn * Tn];  // k1 partials
__device__ float g_e[Bn * Fn];        // logits

__device__ __forceinline__ float tanh_fast(float x) {
    float y; asm("tanh.approx.f32 %0, %1;" : "=f"(y) : "f"(x)); return y;
}
__device__ __forceinline__ uint32_t f2tf32(float v) {
    uint32_t u; asm("cvt.rna.tf32.f32 %0, %1;" : "=r"(u) : "f"(v)); return u;
}
// D[16x8] += A[16x8] * B[8x8], tf32 inputs, f32 accum (HMMA path, plain sm_80+ PTX)
__device__ __forceinline__ void mma_tf32(float* d, const uint4& a, const uint2& b) {
    asm volatile(
        "mma.sync.aligned.m16n8k8.row.col.f32.tf32.tf32.f32 "
        "{%0,%1,%2,%3}, {%4,%5,%6,%7}, {%8,%9}, {%0,%1,%2,%3};"
        : "+f"(d[0]), "+f"(d[1]), "+f"(d[2]), "+f"(d[3])
        : "r"(a.x), "r"(a.y), "r"(a.z), "r"(a.w), "r"(b.x), "r"(b.y));
}

// ---------------------------------------------------------------------------
// k1: partial c[b,t]. grid (KSP, Bn/8). CTA: 8 batches x 128 t x 256 k-slice.
// ---------------------------------------------------------------------------
#define BT1 8
__global__ __launch_bounds__(256) void k1_c(
    const float* __restrict__ h, const float* __restrict__ s,
    const float* __restrict__ W1, const float* __restrict__ b1) {
    __shared__ float hs[BT1 * 256];
    int tid = threadIdx.x;
    int ks = blockIdx.x;
    int b0 = blockIdx.y * BT1;

    for (int i = tid; i < BT1 * 64; i += 256) {
        int bb = i >> 6, j4l = i & 63;
        int jj = ks * 64 + j4l;
        float4 v;
        if (jj < 128) v = __ldg((const float4*)(h + (size_t)(b0 + bb) * Hn) + jj);
        else          v = __ldg((const float4*)(s + (size_t)(b0 + bb) * Hn) + (jj - 128));
        ((float4*)hs)[bb * 64 + j4l] = v;
    }
    __syncthreads();

    int t = tid >> 1, half = tid & 1;
    const float4* w4 = (const float4*)(W1 + (size_t)t * IN1 + Tn + ks * 256);
    float acc[BT1];
    #pragma unroll
    for (int bb = 0; bb < BT1; bb++) acc[bb] = 0.f;

    #pragma unroll 4
    for (int j = 0; j < 32; j++) {
        int idx4 = 2 * j + half;
        float4 w = __ldg(&w4[idx4]);
        #pragma unroll
        for (int bb = 0; bb < BT1; bb++) {
            float4 v = ((const float4*)hs)[bb * 64 + idx4];
            acc[bb] += w.x * v.x + w.y * v.y + w.z * v.z + w.w * v.w;
        }
    }
    #pragma unroll
    for (int bb = 0; bb < BT1; bb++)
        acc[bb] += __shfl_xor_sync(0xffffffffu, acc[bb], 1);
    if (!half) {
        float bias = (ks == 0) ? b1[t] : 0.f;
        #pragma unroll
        for (int bb = 0; bb < BT1; bb++)
            g_cp[ks][(b0 + bb) * Tn + t] = acc[bb] + bias;
    }
}

// ---------------------------------------------------------------------------
// k2: mma.sync tf32. CTA = (f-tile of 128, batch b). 8 warps = 2(M) x 4(N).
// D[t=128, f=128] = W1[:, :128] @ x[b, :, f-tile]; epilogue tanh*W2 reduce.
// A/B staged in smem in mma FRAGMENT layout (consumer: LDS.128/LDS.64 only).
// ---------------------------------------------------------------------------
__global__ __launch_bounds__(256, 2) void k2_main(
    const float* __restrict__ x, const float* __restrict__ W1,
    const float* __restrict__ W2, const float* __restrict__ b2) {
    // A frag region (mt,ks): 32 lanes x 4 regs;  B frag region (nt,ks): 32 x 2
    __shared__ __align__(16) uint32_t Af[8 * 4 * 128];  // 16KB
    __shared__ __align__(16) uint32_t Bf[16 * 4 * 64];  // 16KB
    __shared__ float c_s[Tn], w2_s[Tn];
    __shared__ float red2[2][128];

    int tid = threadIdx.x;
    int w = tid >> 5, lane = tid & 31;
    int wm = w >> 2, wn = w & 3;
    int g = lane >> 2, tq = lane & 3;
    int b  = blockIdx.y;
    int f0 = blockIdx.x * 128;

    if (tid < Tn) {
        float c = 0.f;
        #pragma unroll
        for (int k = 0; k < KSP; k++) c += g_cp[k][b * Tn + tid];
        c_s[tid]  = c;
        w2_s[tid] = __ldg(&W2[tid]);
    }

    float acc[4][4][4];
    #pragma unroll
    for (int i = 0; i < 4; i++)
        #pragma unroll
        for (int j = 0; j < 4; j++)
            #pragma unroll
            for (int r = 0; r < 4; r++) acc[i][j][r] = 0.f;

    const float* xb = x + (size_t)b * Tn * Fn;

    for (int kc = 0; kc < Tn; kc += 32) {
        __syncthreads();
        // ---- stage A: warp w handles mt = w (rows w*16..w*16+15) ----
        {
            const float* r0 = W1 + (size_t)(w * 16 + g) * IN1;
            const float* r8 = r0 + 8 * IN1;
            #pragma unroll
            for (int ks = 0; ks < 4; ks++) {
                int c0 = kc + ks * 8 + tq;
                uint4 v;
                v.x = f2tf32(__ldg(r0 + c0));
                v.y = f2tf32(__ldg(r8 + c0));
                v.z = f2tf32(__ldg(r0 + c0 + 4));
                v.w = f2tf32(__ldg(r8 + c0 + 4));
                *(uint4*)&Af[(w * 4 + ks) * 128 + lane * 4] = v;
            }
        }
        // ---- stage B: warp w handles nt = 2w, 2w+1 ----
        #pragma unroll
        for (int jj = 0; jj < 2; jj++) {
            int nt = w * 2 + jj;
            const float* col = xb + f0 + nt * 8 + g;
            #pragma unroll
            for (int ks = 0; ks < 4; ks++) {
                int k = kc + ks * 8 + tq;
                uint2 v;
                v.x = f2tf32(__ldg(col + (size_t)k * Fn));
                v.y = f2tf32(__ldg(col + (size_t)(k + 4) * Fn));
                *(uint2*)&Bf[(nt * 4 + ks) * 64 + lane * 2] = v;
            }
        }
        __syncthreads();

        // ---- mma mainloop ----
        #pragma unroll
        for (int ks = 0; ks < 4; ks++) {
            uint4 a[4];
            uint2 bb[4];
            #pragma unroll
            for (int i = 0; i < 4; i++)
                a[i] = *(const uint4*)&Af[((wm * 4 + i) * 4 + ks) * 128 + lane * 4];
            #pragma unroll
            for (int j = 0; j < 4; j++)
                bb[j] = *(const uint2*)&Bf[((wn * 4 + j) * 4 + ks) * 64 + lane * 2];
            #pragma unroll
            for (int i = 0; i < 4; i++)
                #pragma unroll
                for (int j = 0; j < 4; j++)
                    mma_tf32(acc[i][j], a[i], bb[j]);
        }
    }

    // ---- epilogue: e[f] = b2 + sum_t W2[t] * tanh(D[t][f] + c[t]) ----
    float b2v = __ldg(&b2[0]);
    float es[4][2];
    #pragma unroll
    for (int j = 0; j < 4; j++) { es[j][0] = 0.f; es[j][1] = 0.f; }
    #pragma unroll
    for (int i = 0; i < 4; i++) {
        int t0 = (wm * 4 + i) * 16 + g;
        float c0 = c_s[t0],     w0 = w2_s[t0];
        float c1 = c_s[t0 + 8], w1 = w2_s[t0 + 8];
        #pragma unroll
        for (int j = 0; j < 4; j++) {
            es[j][0] += w0 * tanh_fast(acc[i][j][0] + c0)
                      + w1 * tanh_fast(acc[i][j][2] + c1);
            es[j][1] += w0 * tanh_fast(acc[i][j][1] + c0)
                      + w1 * tanh_fast(acc[i][j][3] + c1);
        }
    }
    // reduce over g (lane>>2) -> lanes 0..3 hold warp sums (64 t rows)
    #pragma unroll
    for (int j = 0; j < 4; j++)
        #pragma unroll
        for (int s2 = 0; s2 < 2; s2++) {
            float v = es[j][s2];
            v += __shfl_xor_sync(0xffffffffu, v, 4);
            v += __shfl_xor_sync(0xffffffffu, v, 8);
            v += __shfl_xor_sync(0xffffffffu, v, 16);
            es[j][s2] = v;
        }
    if (lane < 4) {
        #pragma unroll
        for (int j = 0; j < 4; j++) {
            int fl = (wn * 4 + j) * 8 + 2 * lane;
            red2[wm][fl]     = es[j][0];
            red2[wm][fl + 1] = es[j][1];
        }
    }
    __syncthreads();
    if (tid < 128)
        g_e[b * Fn + f0 + tid] = red2[0][tid] + red2[1][tid] + b2v;
}

// ---------------------------------------------------------------------------
// k3: softmax over f per batch
// ---------------------------------------------------------------------------
__global__ void k3_softmax(float* __restrict__ out) {
    __shared__ float smr[256];
    int b = blockIdx.x, tid = threadIdx.x;
    const float* eb = g_e + b * Fn;
    float v[4];
    float m = -1e30f;
    #pragma unroll
    for (int i = 0; i < 4; i++) { v[i] = eb[tid + i * 256]; m = fmaxf(m, v[i]); }
    smr[tid] = m; __syncthreads();
    for (int st = 128; st > 0; st >>= 1) {
        if (tid < st) smr[tid] = fmaxf(smr[tid], smr[tid + st]);
        __syncthreads();
    }
    m = smr[0];
    __syncthreads();
    float sum = 0.f;
    #pragma unroll
    for (int i = 0; i < 4; i++) { v[i] = __expf(v[i] - m); sum += v[i]; }
    smr[tid] = sum; __syncthreads();
    for (int st = 128; st > 0; st >>= 1) {
        if (tid < st) smr[tid] += smr[tid + st];
        __syncthreads();
    }
    float inv = 1.f / smr[0];
    #pragma unroll
    for (int i = 0; i < 4; i++) out[b * Fn + tid + i * 256] = v[i] * inv;
}

extern "C" void kernel_launch(void* const* d_in, const int* in_sizes, int n_in,
                              void* d_out, int out_size) {
    const float* h  = (const float*)d_in[0];
    const float* s  = (const float*)d_in[1];
    const float* x  = (const float*)d_in[2];
    const float* W1 = (const float*)d_in[3];
    const float* b1 = (const float*)d_in[4];
    const float* W2 = (const float*)d_in[5];
    const float* b2 = (const float*)d_in[6];
    float* out = (float*)d_out;

    dim3 g1(KSP, Bn / BT1);
    k1_c<<<g1, 256>>>(h, s, W1, b1);
    dim3 g2(Fn / 128, Bn);
    k2_main<<<g2, 256>>>(x, W1, W2, b2);
    k3_softmax<<<Bn, 256>>>(out);
}